// round 8
// baseline (speedup 1.0000x reference)
#include <cuda_runtime.h>
#include <math.h>
#include <stdint.h>

#define NN    50000
#define NE    1000000
#define NG    256
#define ORIG  92
#define ATOMD 64
#define NBR   41
#define FCO   128
#define EPS   1e-5f

// ---------------- scratch (static device globals; no allocation) -------------
__device__ float  g_af[NN * ATOMD];          // atom_fea
__device__ float  g_A1[NN * FCO];            // atom_fea @ fc_W[0:64]
__device__ float  g_A2[NN * FCO];            // atom_fea @ fc_W[64:128]
__device__ float  g_h[(size_t)NE * FCO];     // pre-BN edge hidden (512 MB)
__device__ float  g_summed[NN * ATOMD];      // segment_sum(msg, src)
__device__ float  g_hnode[NN * ATOMD];       // silu(atom_out)
__device__ float  g_logits[NN];
__device__ double g_s1[FCO], g_q1[FCO];      // bn1 sum / sumsq
__device__ double g_s2[ATOMD], g_q2[ATOMD];  // bn2 sum / sumsq
__device__ float  g_bn1_scale[FCO], g_bn1_shift[FCO];
__device__ float  g_bn2_scale[ATOMD], g_bn2_shift[ATOMD];

// ---------------- K0: zero the per-launch accumulators -----------------------
__global__ void k_init() {
    int stride = gridDim.x * blockDim.x;
    for (int i = blockIdx.x * blockDim.x + threadIdx.x; i < NN * ATOMD; i += stride)
        g_summed[i] = 0.f;
    int t = blockIdx.x * blockDim.x + threadIdx.x;
    if (t < FCO)   { g_s1[t] = 0.0; g_q1[t] = 0.0; }
    if (t < ATOMD) { g_s2[t] = 0.0; g_q2[t] = 0.0; }
}

// ---------------- K1a: atom_fea = x @ emb_W + emb_b + lower_f ----------------
#define NPB 16
__global__ void k_embed(const float* __restrict__ x,
                        const float* __restrict__ lower_f,
                        const float* __restrict__ embW,
                        const float* __restrict__ embB) {
    __shared__ __align__(16) float embW_s[ORIG * ATOMD];   // 23552 B
    __shared__ __align__(16) float x_s[NPB * ORIG];        // 5888 B
    int tid = threadIdx.x;  // 256
    int n0  = blockIdx.x * NPB;
    for (int i = tid; i < ORIG * ATOMD; i += 256) embW_s[i] = embW[i];
    for (int i = tid; i < NPB * ORIG; i += 256) {
        int node = n0 + i / ORIG;
        x_s[i] = (node < NN) ? x[node * ORIG + (i % ORIG)] : 0.f;
    }
    __syncthreads();
    for (int t = tid; t < NPB * ATOMD; t += 256) {
        int i = t >> 6, c = t & 63, node = n0 + i;
        if (node >= NN) continue;
        float acc = 0.f;
        const float4* x4 = (const float4*)(x_s + i * ORIG);
#pragma unroll
        for (int k4 = 0; k4 < ORIG / 4; k4++) {
            float4 xv = x4[k4];
            int k = k4 * 4;
            acc += xv.x * embW_s[(k + 0) * ATOMD + c];
            acc += xv.y * embW_s[(k + 1) * ATOMD + c];
            acc += xv.z * embW_s[(k + 2) * ATOMD + c];
            acc += xv.w * embW_s[(k + 3) * ATOMD + c];
        }
        g_af[node * ATOMD + c] = acc + embB[c] + lower_f[node * ATOMD + c];
    }
}

// ---------------- K1b: A1/A2 = atom_fea @ Wa/Wb (register-tiled) -------------
__global__ void k_proj(const float* __restrict__ fcW) {
    __shared__ __align__(16) float W_s[ATOMD * FCO];   // 32 KB
    __shared__ __align__(16) float at_s[NPB * ATOMD];  // 4 KB
    int tid   = threadIdx.x;        // 256
    int which = blockIdx.y;         // 0 -> A1 (rows 0..63), 1 -> A2 (rows 64..127)
    int n0    = blockIdx.x * NPB;
    const float* Wsrc = fcW + which * ATOMD * FCO;
    for (int i = tid; i < ATOMD * FCO; i += 256) W_s[i] = Wsrc[i];
    for (int i = tid; i < NPB * ATOMD; i += 256) {
        int node = n0 + (i >> 6);
        at_s[i] = (node < NN) ? g_af[node * ATOMD + (i & 63)] : 0.f;
    }
    __syncthreads();
    int j = tid & 127, ig = tid >> 7;   // 2 node-groups of 8
    float acc[8];
#pragma unroll
    for (int r = 0; r < 8; r++) acc[r] = 0.f;
    for (int c = 0; c < ATOMD; c++) {
        float w = W_s[c * FCO + j];
#pragma unroll
        for (int r = 0; r < 8; r++)
            acc[r] += at_s[(ig + 2 * r) * ATOMD + c] * w;
    }
    float* dst = which ? g_A2 : g_A1;
#pragma unroll
    for (int r = 0; r < 8; r++) {
        int node = n0 + ig + 2 * r;
        if (node < NN) dst[node * FCO + j] = acc[r];
    }
}

// ---------------- K2: edge pass 1 — h = A1[src]+A2[dst]+attr@W3+b, stats -----
// Weights in SHARED MEMORY (LDS.128 amortized over edge unroll), f32x2 FMAs,
// 256-thread blocks (2 column-groups x 4 edges), low register pressure for
// high occupancy. Double-buffered attr staging.
#define EPB 256
#define ECH 8
__global__ void __launch_bounds__(256) k_edge1(const float* __restrict__ eattr,
                        const int* __restrict__ eidx,
                        const float* __restrict__ fcW,
                        const float* __restrict__ fcB) {
    // w4s[j][c] = (W[4j,c], W[4j+1,c], W[4j+2,c], W[4j+3,c]); rows >=41 are 0
    __shared__ __align__(16) float4 w4s[11][FCO];        // 22528 B
    __shared__ __align__(16) float attr_s[2][ECH][44];   // 2816 B (cols 41..43 = 0)
    __shared__ int src_s[2][ECH], dst_s[2][ECH];

    int tid = threadIdx.x;       // 256
    int grp = tid >> 7;          // 0..1: edge sub-group (4 edges each)
    int c   = tid & 127;         // output column

    // load packed weights into smem
    for (int idx = tid; idx < 11 * FCO; idx += 256) {
        int j = idx >> 7, cc = idx & 127;
        float4 v;
        v.x = (4 * j + 0 < NBR) ? fcW[(FCO + 4 * j + 0) * FCO + cc] : 0.f;
        v.y = (4 * j + 1 < NBR) ? fcW[(FCO + 4 * j + 1) * FCO + cc] : 0.f;
        v.z = (4 * j + 2 < NBR) ? fcW[(FCO + 4 * j + 2) * FCO + cc] : 0.f;
        v.w = (4 * j + 3 < NBR) ? fcW[(FCO + 4 * j + 3) * FCO + cc] : 0.f;
        w4s[j][cc] = v;
    }
    // zero attr padding columns (41..43) in both buffers, once
    if (tid < 2 * ECH * 3) {
        int b = tid / (ECH * 3), r = tid % (ECH * 3);
        attr_s[b][r / 3][41 + (r % 3)] = 0.f;
    }

    float b = fcB[c];
    float s0 = 0.f, s1 = 0.f, q0 = 0.f, q1 = 0.f;

    int e0 = blockIdx.x * EPB;
    int remaining = NE - e0;

    auto stage = [&](int bi, int ce0) {
        for (int t = tid; t < ECH * NBR; t += 256) {
            int i = t / NBR, k = t - i * NBR;
            float v = 0.f;
            if (ce0 + i < NE) v = eattr[(size_t)ce0 * NBR + t];
            attr_s[bi][i][k] = v;
        }
        if (tid < ECH) {
            int e = ce0 + tid;
            src_s[bi][tid] = (e < NE) ? eidx[e] : 0;
        } else if (tid < 2 * ECH) {
            int e = ce0 + tid - ECH;
            dst_s[bi][tid - ECH] = (e < NE) ? eidx[NE + e] : 0;
        }
    };

    // compute h for one staged edge (pair-packed dot over 41 attrs)
    auto edge_h = [&](int buf, int i, float base) -> float {
        unsigned long long acc;
        asm("mov.b64 %0, {%1,%2};" : "=l"(acc) : "f"(base), "f"(0.0f));
#pragma unroll
        for (int jj = 0; jj < 10; jj++) {
            ulonglong2 w = *(const ulonglong2*)&w4s[jj][c];              // LDS.128
            ulonglong2 a = *(const ulonglong2*)&attr_s[buf][i][4 * jj];  // LDS.128
            asm("fma.rn.f32x2 %0, %1, %2, %0;" : "+l"(acc) : "l"(a.x), "l"(w.x));
            asm("fma.rn.f32x2 %0, %1, %2, %0;" : "+l"(acc) : "l"(a.y), "l"(w.y));
        }
        {   // k = 40 (+ zero pad 41)
            unsigned long long w = *(const unsigned long long*)&w4s[10][c];
            unsigned long long a = *(const unsigned long long*)&attr_s[buf][i][40];
            asm("fma.rn.f32x2 %0, %1, %2, %0;" : "+l"(acc) : "l"(a), "l"(w));
        }
        float lo, hi;
        asm("mov.b64 {%0,%1}, %2;" : "=f"(lo), "=f"(hi) : "l"(acc));
        return lo + hi;
    };

    stage(0, e0);
    __syncthreads();

    const int nch = EPB / ECH;   // 32
    for (int ch = 0; ch < nch; ch++) {
        int buf = ch & 1;
        if (ch + 1 < nch) stage(buf ^ 1, e0 + (ch + 1) * ECH);

        int cbase = ch * ECH;
        if (cbase + ECH <= remaining) {
            // full chunk: this thread handles edges grp*4 .. grp*4+3
#pragma unroll
            for (int u = 0; u < 4; u++) {
                int i = grp * 4 + u;
                float base = b + g_A1[src_s[buf][i] * FCO + c]
                               + g_A2[dst_s[buf][i] * FCO + c];
                float h = edge_h(buf, i, base);
                g_h[(size_t)(e0 + cbase + i) * FCO + c] = h;
                if (u & 1) { s1 += h; q1 = fmaf(h, h, q1); }
                else       { s0 += h; q0 = fmaf(h, h, q0); }
            }
        } else if (cbase < remaining) {
            int cnt = remaining - cbase;
            for (int u = 0; u < 4; u++) {
                int i = grp * 4 + u;
                if (i < cnt) {
                    float base = b + g_A1[src_s[buf][i] * FCO + c]
                                   + g_A2[dst_s[buf][i] * FCO + c];
                    float h = edge_h(buf, i, base);
                    g_h[(size_t)(e0 + cbase + i) * FCO + c] = h;
                    s0 += h; q0 = fmaf(h, h, q0);
                }
            }
        }
        __syncthreads();
    }
    atomicAdd(&g_s1[c], (double)(s0 + s1));
    atomicAdd(&g_q1[c], (double)(q0 + q1));
}

// ---------------- K3: finalize bn1 scale/shift --------------------------------
__global__ void k_bn1fin(const float* __restrict__ g1, const float* __restrict__ b1) {
    int c = threadIdx.x;
    double mean = g_s1[c] / (double)NE;
    double var  = g_q1[c] / (double)NE - mean * mean;
    float sc = g1[c] * (float)(1.0 / sqrt(var + (double)EPS));
    g_bn1_scale[c] = sc;
    g_bn1_shift[c] = b1[c] - (float)mean * sc;
}

__device__ __forceinline__ float sigm(float x)  { return __fdividef(1.f, 1.f + __expf(-x)); }
__device__ __forceinline__ float softp(float x) { return fmaxf(x, 0.f) + __logf(1.f + __expf(-fabsf(x))); }

// ---------------- K4: edge pass 2 — msg + scatter into summed ----------------
__global__ void k_edge2(const int* __restrict__ eidx) {
    int gtid = blockIdx.x * blockDim.x + threadIdx.x;
    int e = gtid >> 4;          // 16 threads per edge
    int q = gtid & 15;          // 4 columns per thread
    if (e >= NE) return;
    const float4* h4 = (const float4*)(g_h + (size_t)e * FCO);
    float4 hf = h4[q];
    float4 hc = h4[16 + q];
    int c0 = q * 4;
    float4 m;
    {
        float f0 = g_bn1_scale[c0 + 0] * hf.x + g_bn1_shift[c0 + 0];
        float f1 = g_bn1_scale[c0 + 1] * hf.y + g_bn1_shift[c0 + 1];
        float f2 = g_bn1_scale[c0 + 2] * hf.z + g_bn1_shift[c0 + 2];
        float f3 = g_bn1_scale[c0 + 3] * hf.w + g_bn1_shift[c0 + 3];
        float g0 = g_bn1_scale[64 + c0 + 0] * hc.x + g_bn1_shift[64 + c0 + 0];
        float g1 = g_bn1_scale[64 + c0 + 1] * hc.y + g_bn1_shift[64 + c0 + 1];
        float g2 = g_bn1_scale[64 + c0 + 2] * hc.z + g_bn1_shift[64 + c0 + 2];
        float g3 = g_bn1_scale[64 + c0 + 3] * hc.w + g_bn1_shift[64 + c0 + 3];
        m.x = sigm(f0) * softp(g0);
        m.y = sigm(f1) * softp(g1);
        m.z = sigm(f2) * softp(g2);
        m.w = sigm(f3) * softp(g3);
    }
    int src = eidx[e];
    float* dst = g_summed + src * ATOMD + c0;
    asm volatile("red.global.add.v4.f32 [%0], {%1,%2,%3,%4};"
                 :: "l"(dst), "f"(m.x), "f"(m.y), "f"(m.z), "f"(m.w) : "memory");
}

// ---------------- K5: bn2 stats over summed -----------------------------------
__global__ void k_bn2stats() {
    int c    = threadIdx.x & 63;
    int row0 = blockIdx.x * (blockDim.x >> 6) + (threadIdx.x >> 6);
    int strd = gridDim.x * (blockDim.x >> 6);
    float s = 0.f, q = 0.f;
    for (int r = row0; r < NN; r += strd) {
        float v = g_summed[r * ATOMD + c];
        s += v; q += v * v;
    }
    atomicAdd(&g_s2[c], (double)s);
    atomicAdd(&g_q2[c], (double)q);
}

__global__ void k_bn2fin(const float* __restrict__ g2, const float* __restrict__ b2) {
    int c = threadIdx.x;
    double mean = g_s2[c] / (double)NN;
    double var  = g_q2[c] / (double)NN - mean * mean;
    float sc = g2[c] * (float)(1.0 / sqrt(var + (double)EPS));
    g_bn2_scale[c] = sc;
    g_bn2_shift[c] = b2[c] - (float)mean * sc;
}

// ---------------- K6: atom_out + silu + logits ---------------------------------
__global__ void k_node2(float* __restrict__ out,
                        const float* __restrict__ attW,
                        const float* __restrict__ attB) {
    int tid  = threadIdx.x;          // 256 -> 4 nodes
    int node = blockIdx.x * 4 + (tid >> 6);
    int c    = tid & 63;
    __shared__ float sh[4][2];
    float part = 0.f;
    if (node < NN) {
        float v  = g_summed[node * ATOMD + c];
        float ao = g_bn2_scale[c] * v + g_bn2_shift[c];
        out[node * ATOMD + c] = ao;
        float h = ao * sigm(ao);
        g_hnode[node * ATOMD + c] = h;
        part = h * attW[c];
    }
#pragma unroll
    for (int off = 16; off; off >>= 1)
        part += __shfl_down_sync(0xffffffff, part, off);
    if ((tid & 31) == 0) sh[tid >> 6][(tid >> 5) & 1] = part;
    __syncthreads();
    if (tid < 4) {
        int n2 = blockIdx.x * 4 + tid;
        if (n2 < NN) g_logits[n2] = sh[tid][0] + sh[tid][1] + attB[0];
    }
}

// ---------------- K7: per-graph softmax attention pooling ----------------------
__global__ void k_graph(float* __restrict__ out,
                        const int* __restrict__ batch,
                        const float* __restrict__ outW,
                        const float* __restrict__ outB) {
    int g   = blockIdx.x;
    int tid = threadIdx.x;           // 128
    __shared__ int lo_s, hi_s;
    __shared__ float red[128];
    if (tid == 0) {
        int lo = 0, hi = NN;
        while (lo < hi) { int md = (lo + hi) >> 1; if (batch[md] < g) lo = md + 1; else hi = md; }
        lo_s = lo;
        int lo2 = lo, hi2 = NN;
        while (lo2 < hi2) { int md = (lo2 + hi2) >> 1; if (batch[md] < g + 1) lo2 = md + 1; else hi2 = md; }
        hi_s = lo2;
    }
    __syncthreads();
    int lo = lo_s, hi = hi_s;
    if (lo >= hi) { if (tid == 0) out[NN * ATOMD + g] = outB[0]; return; }

    float m = -INFINITY;
    for (int n = lo + tid; n < hi; n += 128) m = fmaxf(m, g_logits[n]);
    red[tid] = m; __syncthreads();
    for (int s = 64; s; s >>= 1) { if (tid < s) red[tid] = fmaxf(red[tid], red[tid + s]); __syncthreads(); }
    m = red[0]; __syncthreads();

    float ssum = 0.f;
    for (int n = lo + tid; n < hi; n += 128) ssum += expf(g_logits[n] - m);
    red[tid] = ssum; __syncthreads();
    for (int s = 64; s; s >>= 1) { if (tid < s) red[tid] += red[tid + s]; __syncthreads(); }
    float denom = red[0]; __syncthreads();

    int c = tid & 63, half = tid >> 6;
    float acc = 0.f;
    for (int n = lo + half; n < hi; n += 2) {
        float alpha = expf(g_logits[n] - m) / denom;
        acc += alpha * g_hnode[n * ATOMD + c];
    }
    red[tid] = acc * outW[c]; __syncthreads();
    for (int s = 64; s; s >>= 1) { if (tid < s) red[tid] += red[tid + s]; __syncthreads(); }
    if (tid == 0) out[NN * ATOMD + g] = red[0] + outB[0];
}

// ---------------- launch --------------------------------------------------------
extern "C" void kernel_launch(void* const* d_in, const int* in_sizes, int n_in,
                              void* d_out, int out_size) {
    const float *x, *eattr, *lowf, *embW, *embB, *fcW, *fcB;
    const float *bn1g, *bn1b, *bn2g, *bn2b, *attW, *attB, *outW, *outB;
    const int *eidx, *batch;

    if (in_sizes[3] == 2 * NE) {
        // setup_inputs dict order
        x     = (const float*)d_in[0];  eattr = (const float*)d_in[1];
        lowf  = (const float*)d_in[2];  eidx  = (const int*)  d_in[3];
        batch = (const int*)  d_in[4];  embW  = (const float*)d_in[5];
        embB  = (const float*)d_in[6];  fcW   = (const float*)d_in[7];
        fcB   = (const float*)d_in[8];  bn1g  = (const float*)d_in[9];
        bn1b  = (const float*)d_in[10]; bn2g  = (const float*)d_in[11];
        bn2b  = (const float*)d_in[12]; attW  = (const float*)d_in[13];
        attB  = (const float*)d_in[14]; outW  = (const float*)d_in[15];
        outB  = (const float*)d_in[16];
    } else {
        // reference-signature order
        x     = (const float*)d_in[0];  eattr = (const float*)d_in[1];
        lowf  = (const float*)d_in[2];  embW  = (const float*)d_in[3];
        embB  = (const float*)d_in[4];  fcW   = (const float*)d_in[5];
        fcB   = (const float*)d_in[6];  bn1g  = (const float*)d_in[7];
        bn1b  = (const float*)d_in[8];  bn2g  = (const float*)d_in[9];
        bn2b  = (const float*)d_in[10]; attW  = (const float*)d_in[11];
        attB  = (const float*)d_in[12]; outW  = (const float*)d_in[13];
        outB  = (const float*)d_in[14]; eidx  = (const int*)  d_in[15];
        batch = (const int*)  d_in[16];
    }

    float* out = (float*)d_out;

    k_init<<<2048, 512>>>();
    k_embed<<<(NN + NPB - 1) / NPB, 256>>>(x, lowf, embW, embB);
    {
        dim3 grid((NN + NPB - 1) / NPB, 2);
        k_proj<<<grid, 256>>>(fcW);
    }
    k_edge1<<<(NE + EPB - 1) / EPB, 256>>>(eattr, eidx, fcW, fcB);
    k_bn1fin<<<1, FCO>>>(bn1g, bn1b);
    k_edge2<<<(NE * 16 + 255) / 256, 256>>>(eidx);
    k_bn2stats<<<128, 256>>>();
    k_bn2fin<<<1, ATOMD>>>(bn2g, bn2b);
    k_node2<<<(NN + 3) / 4, 256>>>(out, attW, attB);
    k_graph<<<NG, 128>>>(out, batch, outW, outB);
}

// round 9
// speedup vs baseline: 1.0666x; 1.0666x over previous
#include <cuda_runtime.h>
#include <math.h>
#include <stdint.h>

#define NN    50000
#define NE    1000000
#define NG    256
#define ORIG  92
#define ATOMD 64
#define NBR   41
#define FCO   128
#define EPS   1e-5f

// ---------------- scratch (static device globals; no allocation) -------------
__device__ float  g_af[NN * ATOMD];          // atom_fea
__device__ float  g_A1[NN * FCO];            // atom_fea @ fc_W[0:64]
__device__ float  g_A2[NN * FCO];            // atom_fea @ fc_W[64:128]
__device__ float  g_h[(size_t)NE * FCO];     // pre-BN edge hidden (512 MB)
__device__ float  g_summed[NN * ATOMD];      // segment_sum(msg, src)
__device__ float  g_hnode[NN * ATOMD];       // silu(atom_out)
__device__ float  g_logits[NN];
__device__ double g_s1[FCO], g_q1[FCO];      // bn1 sum / sumsq
__device__ double g_s2[ATOMD], g_q2[ATOMD];  // bn2 sum / sumsq
__device__ float  g_bn1_scale[FCO], g_bn1_shift[FCO];
__device__ float  g_bn2_scale[ATOMD], g_bn2_shift[ATOMD];

// ---------------- K0: zero the per-launch accumulators -----------------------
__global__ void k_init() {
    int stride = gridDim.x * blockDim.x;
    for (int i = blockIdx.x * blockDim.x + threadIdx.x; i < NN * ATOMD; i += stride)
        g_summed[i] = 0.f;
    int t = blockIdx.x * blockDim.x + threadIdx.x;
    if (t < FCO)   { g_s1[t] = 0.0; g_q1[t] = 0.0; }
    if (t < ATOMD) { g_s2[t] = 0.0; g_q2[t] = 0.0; }
}

// ---------------- K1a: atom_fea = x @ emb_W + emb_b + lower_f ----------------
#define NPB 16
__global__ void k_embed(const float* __restrict__ x,
                        const float* __restrict__ lower_f,
                        const float* __restrict__ embW,
                        const float* __restrict__ embB) {
    __shared__ __align__(16) float embW_s[ORIG * ATOMD];   // 23552 B
    __shared__ __align__(16) float x_s[NPB * ORIG];        // 5888 B
    int tid = threadIdx.x;  // 256
    int n0  = blockIdx.x * NPB;
    for (int i = tid; i < ORIG * ATOMD; i += 256) embW_s[i] = embW[i];
    for (int i = tid; i < NPB * ORIG; i += 256) {
        int node = n0 + i / ORIG;
        x_s[i] = (node < NN) ? x[node * ORIG + (i % ORIG)] : 0.f;
    }
    __syncthreads();
    for (int t = tid; t < NPB * ATOMD; t += 256) {
        int i = t >> 6, c = t & 63, node = n0 + i;
        if (node >= NN) continue;
        float acc = 0.f;
        const float4* x4 = (const float4*)(x_s + i * ORIG);
#pragma unroll
        for (int k4 = 0; k4 < ORIG / 4; k4++) {
            float4 xv = x4[k4];
            int k = k4 * 4;
            acc += xv.x * embW_s[(k + 0) * ATOMD + c];
            acc += xv.y * embW_s[(k + 1) * ATOMD + c];
            acc += xv.z * embW_s[(k + 2) * ATOMD + c];
            acc += xv.w * embW_s[(k + 3) * ATOMD + c];
        }
        g_af[node * ATOMD + c] = acc + embB[c] + lower_f[node * ATOMD + c];
    }
}

// ---------------- K1b: A1/A2 = atom_fea @ Wa/Wb (register-tiled) -------------
__global__ void k_proj(const float* __restrict__ fcW) {
    __shared__ __align__(16) float W_s[ATOMD * FCO];   // 32 KB
    __shared__ __align__(16) float at_s[NPB * ATOMD];  // 4 KB
    int tid   = threadIdx.x;        // 256
    int which = blockIdx.y;         // 0 -> A1 (rows 0..63), 1 -> A2 (rows 64..127)
    int n0    = blockIdx.x * NPB;
    const float* Wsrc = fcW + which * ATOMD * FCO;
    for (int i = tid; i < ATOMD * FCO; i += 256) W_s[i] = Wsrc[i];
    for (int i = tid; i < NPB * ATOMD; i += 256) {
        int node = n0 + (i >> 6);
        at_s[i] = (node < NN) ? g_af[node * ATOMD + (i & 63)] : 0.f;
    }
    __syncthreads();
    int j = tid & 127, ig = tid >> 7;   // 2 node-groups of 8
    float acc[8];
#pragma unroll
    for (int r = 0; r < 8; r++) acc[r] = 0.f;
    for (int c = 0; c < ATOMD; c++) {
        float w = W_s[c * FCO + j];
#pragma unroll
        for (int r = 0; r < 8; r++)
            acc[r] += at_s[(ig + 2 * r) * ATOMD + c] * w;
    }
    float* dst = which ? g_A2 : g_A1;
#pragma unroll
    for (int r = 0; r < 8; r++) {
        int node = n0 + ig + 2 * r;
        if (node < NN) dst[node * FCO + j] = acc[r];
    }
}

// ---------------- K2: edge pass 1 — h = A1[src]+A2[dst]+attr@W3+b, stats -----
// K-SPLIT design: 256 threads = 2 halves x 128 columns.
//   half 0 (threads   0..127): b + A1[src,c] + attr[0:20)  @ W   (10 f32x2 pairs)
//   half 1 (threads 128..255):     A2[dst,c] + attr[20:42) @ W   (11 pairs, col41=0)
// Halves combine through smem `part`. Per-thread weight regs: 22 (vs 42).
// Chunks are always full (NE, EPB, ECH multiples of 8) -> no edge predication.
#define EPB 512
#define ECH 8
__global__ void __launch_bounds__(256, 5) k_edge1(
                        const float* __restrict__ eattr,
                        const int* __restrict__ eidx,
                        const float* __restrict__ fcW,
                        const float* __restrict__ fcB) {
    __shared__ __align__(16) float attr_s[2][ECH][44];   // cols 41..43 zero
    __shared__ float part[ECH][FCO];                     // half-1 partials
    __shared__ int src_s[2][ECH], dst_s[2][ECH];

    int tid  = threadIdx.x;      // 256
    int half = tid >> 7;         // 0 or 1
    int c    = tid & 127;        // output column

    // per-thread packed weight pairs for this half's k-range
    unsigned long long w2[11];
    if (half == 0) {
#pragma unroll
        for (int j = 0; j < 10; j++) {
            float wa = fcW[(FCO + 2 * j + 0) * FCO + c];
            float wb = fcW[(FCO + 2 * j + 1) * FCO + c];
            asm("mov.b64 %0, {%1,%2};" : "=l"(w2[j]) : "f"(wa), "f"(wb));
        }
        w2[10] = 0ull;
    } else {
#pragma unroll
        for (int j = 0; j < 11; j++) {
            int ka = 20 + 2 * j, kb = 21 + 2 * j;
            float wa = fcW[(FCO + ka) * FCO + c];
            float wb = (kb < NBR) ? fcW[(FCO + kb) * FCO + c] : 0.f;
            asm("mov.b64 %0, {%1,%2};" : "=l"(w2[j]) : "f"(wa), "f"(wb));
        }
    }
    float b = fcB[c];                 // used by half 0 only
    float s = 0.f, q = 0.f;           // stats (half 0 only)
    float hA[ECH];                    // half-0 partials held across sync

    // zero attr padding columns (41..43) in both buffers, once
    if (tid < 2 * ECH * 3) {
        int bb = tid / (ECH * 3), r = tid % (ECH * 3);
        attr_s[bb][r / 3][41 + (r % 3)] = 0.f;
    }

    int e0 = blockIdx.x * EPB;

    // stage chunk starting at ce0 into buffer bi; participants: ltid in [0,nthr)
    auto stage = [&](int bi, int ce0, int ltid, int nthr) {
        if (ce0 >= NE) return;
        for (int t = ltid; t < ECH * NBR; t += nthr) {
            int i = t / NBR, k = t - i * NBR;
            attr_s[bi][i][k] = eattr[(size_t)ce0 * NBR + t];
        }
        if (ltid < ECH)                    src_s[bi][ltid] = eidx[ce0 + ltid];
        else if (ltid < 2 * ECH)           dst_s[bi][ltid - ECH] = eidx[NE + ce0 + ltid - ECH];
    };

    stage(0, e0, tid, 256);
    __syncthreads();

    const int nch = EPB / ECH;   // 64
    for (int ch = 0; ch < nch; ch++) {
        int cur = ch & 1;
        int cb  = e0 + ch * ECH;
        bool valid = (cb < NE);           // chunks are full-or-empty

        if (valid) {
            if (half == 0) {
                // phase 1: dot over k=0..19 plus base (b + A1[src,c])
#pragma unroll
                for (int i = 0; i < ECH; i++) {
                    float a1 = g_A1[src_s[cur][i] * FCO + c];
                    unsigned long long acc;
                    asm("mov.b64 %0, {%1,%2};" : "=l"(acc) : "f"(b + a1), "f"(0.0f));
                    const ulonglong2* a16 = (const ulonglong2*)attr_s[cur][i];
#pragma unroll
                    for (int jj = 0; jj < 5; jj++) {
                        ulonglong2 u = a16[jj];
                        asm("fma.rn.f32x2 %0, %1, %2, %0;" : "+l"(acc) : "l"(u.x), "l"(w2[2 * jj]));
                        asm("fma.rn.f32x2 %0, %1, %2, %0;" : "+l"(acc) : "l"(u.y), "l"(w2[2 * jj + 1]));
                    }
                    float lo, hi;
                    asm("mov.b64 {%0,%1}, %2;" : "=f"(lo), "=f"(hi) : "l"(acc));
                    hA[i] = lo + hi;
                }
            } else {
                // phase 1: dot over k=20..41 (col41=0) plus A2[dst,c] -> smem
#pragma unroll
                for (int i = 0; i < ECH; i++) {
                    float a2 = g_A2[dst_s[cur][i] * FCO + c];
                    unsigned long long acc;
                    asm("mov.b64 %0, {%1,%2};" : "=l"(acc) : "f"(a2), "f"(0.0f));
                    const ulonglong2* a16 = (const ulonglong2*)(attr_s[cur][i] + 20);
#pragma unroll
                    for (int jj = 0; jj < 5; jj++) {
                        ulonglong2 u = a16[jj];
                        asm("fma.rn.f32x2 %0, %1, %2, %0;" : "+l"(acc) : "l"(u.x), "l"(w2[2 * jj]));
                        asm("fma.rn.f32x2 %0, %1, %2, %0;" : "+l"(acc) : "l"(u.y), "l"(w2[2 * jj + 1]));
                    }
                    {
                        unsigned long long u = *(const unsigned long long*)(attr_s[cur][i] + 40);
                        asm("fma.rn.f32x2 %0, %1, %2, %0;" : "+l"(acc) : "l"(u), "l"(w2[10]));
                    }
                    float lo, hi;
                    asm("mov.b64 {%0,%1}, %2;" : "=f"(lo), "=f"(hi) : "l"(acc));
                    part[i][c] = lo + hi;
                }
            }
        }
        __syncthreads();

        if (valid && half == 0) {
            // phase 2 (half 0): combine, store h, stats
#pragma unroll
            for (int i = 0; i < ECH; i++) {
                float h = hA[i] + part[i][c];
                g_h[(size_t)(cb + i) * FCO + c] = h;
                s += h;
                q = fmaf(h, h, q);
            }
        } else if (half == 1) {
            // phase 2 (half 1): stage next chunk's attrs/indices
            if (ch + 1 < nch) stage(cur ^ 1, cb + ECH, tid - 128, 128);
        }
        __syncthreads();
    }
    if (half == 0) {
        atomicAdd(&g_s1[c], (double)s);
        atomicAdd(&g_q1[c], (double)q);
    }
}

// ---------------- K3: finalize bn1 scale/shift --------------------------------
__global__ void k_bn1fin(const float* __restrict__ g1, const float* __restrict__ b1) {
    int c = threadIdx.x;
    double mean = g_s1[c] / (double)NE;
    double var  = g_q1[c] / (double)NE - mean * mean;
    float sc = g1[c] * (float)(1.0 / sqrt(var + (double)EPS));
    g_bn1_scale[c] = sc;
    g_bn1_shift[c] = b1[c] - (float)mean * sc;
}

__device__ __forceinline__ float sigm(float x)  { return __fdividef(1.f, 1.f + __expf(-x)); }
__device__ __forceinline__ float softp(float x) { return fmaxf(x, 0.f) + __logf(1.f + __expf(-fabsf(x))); }

// ---------------- K4: edge pass 2 — msg + scatter into summed ----------------
__global__ void k_edge2(const int* __restrict__ eidx) {
    int gtid = blockIdx.x * blockDim.x + threadIdx.x;
    int e = gtid >> 4;          // 16 threads per edge
    int q = gtid & 15;          // 4 columns per thread
    if (e >= NE) return;
    const float4* h4 = (const float4*)(g_h + (size_t)e * FCO);
    float4 hf = h4[q];
    float4 hc = h4[16 + q];
    int c0 = q * 4;
    float4 m;
    {
        float f0 = g_bn1_scale[c0 + 0] * hf.x + g_bn1_shift[c0 + 0];
        float f1 = g_bn1_scale[c0 + 1] * hf.y + g_bn1_shift[c0 + 1];
        float f2 = g_bn1_scale[c0 + 2] * hf.z + g_bn1_shift[c0 + 2];
        float f3 = g_bn1_scale[c0 + 3] * hf.w + g_bn1_shift[c0 + 3];
        float g0 = g_bn1_scale[64 + c0 + 0] * hc.x + g_bn1_shift[64 + c0 + 0];
        float g1 = g_bn1_scale[64 + c0 + 1] * hc.y + g_bn1_shift[64 + c0 + 1];
        float g2 = g_bn1_scale[64 + c0 + 2] * hc.z + g_bn1_shift[64 + c0 + 2];
        float g3 = g_bn1_scale[64 + c0 + 3] * hc.w + g_bn1_shift[64 + c0 + 3];
        m.x = sigm(f0) * softp(g0);
        m.y = sigm(f1) * softp(g1);
        m.z = sigm(f2) * softp(g2);
        m.w = sigm(f3) * softp(g3);
    }
    int src = eidx[e];
    float* dst = g_summed + src * ATOMD + c0;
    asm volatile("red.global.add.v4.f32 [%0], {%1,%2,%3,%4};"
                 :: "l"(dst), "f"(m.x), "f"(m.y), "f"(m.z), "f"(m.w) : "memory");
}

// ---------------- K5: bn2 stats over summed -----------------------------------
__global__ void k_bn2stats() {
    int c    = threadIdx.x & 63;
    int row0 = blockIdx.x * (blockDim.x >> 6) + (threadIdx.x >> 6);
    int strd = gridDim.x * (blockDim.x >> 6);
    float s = 0.f, q = 0.f;
    for (int r = row0; r < NN; r += strd) {
        float v = g_summed[r * ATOMD + c];
        s += v; q += v * v;
    }
    atomicAdd(&g_s2[c], (double)s);
    atomicAdd(&g_q2[c], (double)q);
}

__global__ void k_bn2fin(const float* __restrict__ g2, const float* __restrict__ b2) {
    int c = threadIdx.x;
    double mean = g_s2[c] / (double)NN;
    double var  = g_q2[c] / (double)NN - mean * mean;
    float sc = g2[c] * (float)(1.0 / sqrt(var + (double)EPS));
    g_bn2_scale[c] = sc;
    g_bn2_shift[c] = b2[c] - (float)mean * sc;
}

// ---------------- K6: atom_out + silu + logits ---------------------------------
__global__ void k_node2(float* __restrict__ out,
                        const float* __restrict__ attW,
                        const float* __restrict__ attB) {
    int tid  = threadIdx.x;          // 256 -> 4 nodes
    int node = blockIdx.x * 4 + (tid >> 6);
    int c    = tid & 63;
    __shared__ float sh[4][2];
    float part = 0.f;
    if (node < NN) {
        float v  = g_summed[node * ATOMD + c];
        float ao = g_bn2_scale[c] * v + g_bn2_shift[c];
        out[node * ATOMD + c] = ao;
        float h = ao * sigm(ao);
        g_hnode[node * ATOMD + c] = h;
        part = h * attW[c];
    }
#pragma unroll
    for (int off = 16; off; off >>= 1)
        part += __shfl_down_sync(0xffffffff, part, off);
    if ((tid & 31) == 0) sh[tid >> 6][(tid >> 5) & 1] = part;
    __syncthreads();
    if (tid < 4) {
        int n2 = blockIdx.x * 4 + tid;
        if (n2 < NN) g_logits[n2] = sh[tid][0] + sh[tid][1] + attB[0];
    }
}

// ---------------- K7: per-graph softmax attention pooling ----------------------
__global__ void k_graph(float* __restrict__ out,
                        const int* __restrict__ batch,
                        const float* __restrict__ outW,
                        const float* __restrict__ outB) {
    int g   = blockIdx.x;
    int tid = threadIdx.x;           // 128
    __shared__ int lo_s, hi_s;
    __shared__ float red[128];
    if (tid == 0) {
        int lo = 0, hi = NN;
        while (lo < hi) { int md = (lo + hi) >> 1; if (batch[md] < g) lo = md + 1; else hi = md; }
        lo_s = lo;
        int lo2 = lo, hi2 = NN;
        while (lo2 < hi2) { int md = (lo2 + hi2) >> 1; if (batch[md] < g + 1) lo2 = md + 1; else hi2 = md; }
        hi_s = lo2;
    }
    __syncthreads();
    int lo = lo_s, hi = hi_s;
    if (lo >= hi) { if (tid == 0) out[NN * ATOMD + g] = outB[0]; return; }

    float m = -INFINITY;
    for (int n = lo + tid; n < hi; n += 128) m = fmaxf(m, g_logits[n]);
    red[tid] = m; __syncthreads();
    for (int s = 64; s; s >>= 1) { if (tid < s) red[tid] = fmaxf(red[tid], red[tid + s]); __syncthreads(); }
    m = red[0]; __syncthreads();

    float ssum = 0.f;
    for (int n = lo + tid; n < hi; n += 128) ssum += expf(g_logits[n] - m);
    red[tid] = ssum; __syncthreads();
    for (int s = 64; s; s >>= 1) { if (tid < s) red[tid] += red[tid + s]; __syncthreads(); }
    float denom = red[0]; __syncthreads();

    int c = tid & 63, half = tid >> 6;
    float acc = 0.f;
    for (int n = lo + half; n < hi; n += 2) {
        float alpha = expf(g_logits[n] - m) / denom;
        acc += alpha * g_hnode[n * ATOMD + c];
    }
    red[tid] = acc * outW[c]; __syncthreads();
    for (int s = 64; s; s >>= 1) { if (tid < s) red[tid] += red[tid + s]; __syncthreads(); }
    if (tid == 0) out[NN * ATOMD + g] = red[0] + outB[0];
}

// ---------------- launch --------------------------------------------------------
extern "C" void kernel_launch(void* const* d_in, const int* in_sizes, int n_in,
                              void* d_out, int out_size) {
    const float *x, *eattr, *lowf, *embW, *embB, *fcW, *fcB;
    const float *bn1g, *bn1b, *bn2g, *bn2b, *attW, *attB, *outW, *outB;
    const int *eidx, *batch;

    if (in_sizes[3] == 2 * NE) {
        // setup_inputs dict order
        x     = (const float*)d_in[0];  eattr = (const float*)d_in[1];
        lowf  = (const float*)d_in[2];  eidx  = (const int*)  d_in[3];
        batch = (const int*)  d_in[4];  embW  = (const float*)d_in[5];
        embB  = (const float*)d_in[6];  fcW   = (const float*)d_in[7];
        fcB   = (const float*)d_in[8];  bn1g  = (const float*)d_in[9];
        bn1b  = (const float*)d_in[10]; bn2g  = (const float*)d_in[11];
        bn2b  = (const float*)d_in[12]; attW  = (const float*)d_in[13];
        attB  = (const float*)d_in[14]; outW  = (const float*)d_in[15];
        outB  = (const float*)d_in[16];
    } else {
        // reference-signature order
        x     = (const float*)d_in[0];  eattr = (const float*)d_in[1];
        lowf  = (const float*)d_in[2];  embW  = (const float*)d_in[3];
        embB  = (const float*)d_in[4];  fcW   = (const float*)d_in[5];
        fcB   = (const float*)d_in[6];  bn1g  = (const float*)d_in[7];
        bn1b  = (const float*)d_in[8];  bn2g  = (const float*)d_in[9];
        bn2b  = (const float*)d_in[10]; attW  = (const float*)d_in[11];
        attB  = (const float*)d_in[12]; outW  = (const float*)d_in[13];
        outB  = (const float*)d_in[14]; eidx  = (const int*)  d_in[15];
        batch = (const int*)  d_in[16];
    }

    float* out = (float*)d_out;

    k_init<<<2048, 512>>>();
    k_embed<<<(NN + NPB - 1) / NPB, 256>>>(x, lowf, embW, embB);
    {
        dim3 grid((NN + NPB - 1) / NPB, 2);
        k_proj<<<grid, 256>>>(fcW);
    }
    k_edge1<<<(NE + EPB - 1) / EPB, 256>>>(eattr, eidx, fcW, fcB);
    k_bn1fin<<<1, FCO>>>(bn1g, bn1b);
    k_edge2<<<(NE * 16 + 255) / 256, 256>>>(eidx);
    k_bn2stats<<<128, 256>>>();
    k_bn2fin<<<1, ATOMD>>>(bn2g, bn2b);
    k_node2<<<(NN + 3) / 4, 256>>>(out, attW, attB);
    k_graph<<<NG, 128>>>(out, batch, outW, outB);
}

// round 11
// speedup vs baseline: 1.3096x; 1.2278x over previous
#include <cuda_runtime.h>
#include <math.h>
#include <stdint.h>

#define NN    50000
#define NE    1000000
#define NG    256
#define ORIG  92
#define ATOMD 64
#define NBR   41
#define FCO   128
#define EPS   1e-5f

// ---------------- scratch (static device globals; no allocation) -------------
__device__ float  g_af[NN * ATOMD];          // atom_fea
__device__ float  g_A1[NN * FCO];            // atom_fea @ fc_W[0:64]
__device__ float  g_A2[NN * FCO];            // atom_fea @ fc_W[64:128]
__device__ float  g_h[(size_t)NE * FCO];     // pre-BN edge hidden (512 MB)
__device__ float  g_summed[NN * ATOMD];      // segment_sum(msg, src)
__device__ float  g_hnode[NN * ATOMD];       // silu(atom_out)
__device__ float  g_logits[NN];
__device__ double g_s1[FCO], g_q1[FCO];      // bn1 sum / sumsq
__device__ double g_s2[ATOMD], g_q2[ATOMD];  // bn2 sum / sumsq
__device__ float  g_bn1_scale[FCO], g_bn1_shift[FCO];
__device__ float  g_bn2_scale[ATOMD], g_bn2_shift[ATOMD];

// ---------------- K0: zero the per-launch accumulators -----------------------
__global__ void k_init() {
    int stride = gridDim.x * blockDim.x;
    for (int i = blockIdx.x * blockDim.x + threadIdx.x; i < NN * ATOMD; i += stride)
        g_summed[i] = 0.f;
    int t = blockIdx.x * blockDim.x + threadIdx.x;
    if (t < FCO)   { g_s1[t] = 0.0; g_q1[t] = 0.0; }
    if (t < ATOMD) { g_s2[t] = 0.0; g_q2[t] = 0.0; }
}

// ---------------- K1a: atom_fea = x @ emb_W + emb_b + lower_f ----------------
#define NPB 16
__global__ void k_embed(const float* __restrict__ x,
                        const float* __restrict__ lower_f,
                        const float* __restrict__ embW,
                        const float* __restrict__ embB) {
    __shared__ __align__(16) float embW_s[ORIG * ATOMD];   // 23552 B
    __shared__ __align__(16) float x_s[NPB * ORIG];        // 5888 B
    int tid = threadIdx.x;  // 256
    int n0  = blockIdx.x * NPB;
    for (int i = tid; i < ORIG * ATOMD; i += 256) embW_s[i] = embW[i];
    for (int i = tid; i < NPB * ORIG; i += 256) {
        int node = n0 + i / ORIG;
        x_s[i] = (node < NN) ? x[node * ORIG + (i % ORIG)] : 0.f;
    }
    __syncthreads();
    for (int t = tid; t < NPB * ATOMD; t += 256) {
        int i = t >> 6, c = t & 63, node = n0 + i;
        if (node >= NN) continue;
        float acc = 0.f;
        const float4* x4 = (const float4*)(x_s + i * ORIG);
#pragma unroll
        for (int k4 = 0; k4 < ORIG / 4; k4++) {
            float4 xv = x4[k4];
            int k = k4 * 4;
            acc += xv.x * embW_s[(k + 0) * ATOMD + c];
            acc += xv.y * embW_s[(k + 1) * ATOMD + c];
            acc += xv.z * embW_s[(k + 2) * ATOMD + c];
            acc += xv.w * embW_s[(k + 3) * ATOMD + c];
        }
        g_af[node * ATOMD + c] = acc + embB[c] + lower_f[node * ATOMD + c];
    }
}

// ---------------- K1b: A1/A2 = atom_fea @ Wa/Wb (register-tiled) -------------
__global__ void k_proj(const float* __restrict__ fcW) {
    __shared__ __align__(16) float W_s[ATOMD * FCO];   // 32 KB
    __shared__ __align__(16) float at_s[NPB * ATOMD];  // 4 KB
    int tid   = threadIdx.x;        // 256
    int which = blockIdx.y;         // 0 -> A1 (rows 0..63), 1 -> A2 (rows 64..127)
    int n0    = blockIdx.x * NPB;
    const float* Wsrc = fcW + which * ATOMD * FCO;
    for (int i = tid; i < ATOMD * FCO; i += 256) W_s[i] = Wsrc[i];
    for (int i = tid; i < NPB * ATOMD; i += 256) {
        int node = n0 + (i >> 6);
        at_s[i] = (node < NN) ? g_af[node * ATOMD + (i & 63)] : 0.f;
    }
    __syncthreads();
    int j = tid & 127, ig = tid >> 7;   // 2 node-groups of 8
    float acc[8];
#pragma unroll
    for (int r = 0; r < 8; r++) acc[r] = 0.f;
    for (int c = 0; c < ATOMD; c++) {
        float w = W_s[c * FCO + j];
#pragma unroll
        for (int r = 0; r < 8; r++)
            acc[r] += at_s[(ig + 2 * r) * ATOMD + c] * w;
    }
    float* dst = which ? g_A2 : g_A1;
#pragma unroll
    for (int r = 0; r < 8; r++) {
        int node = n0 + ig + 2 * r;
        if (node < NN) dst[node * FCO + j] = acc[r];
    }
}

// ---------------- K2: edge pass 1 — h = A1[src]+A2[dst]+attr@W3+b, stats -----
// cp.async (LDGSTS) staging into a 4-deep buffer ring: no LDG->STS register
// dependency, so warps never sleep inside the staging copy. Weights in packed
// f32x2 register pairs (R6 layout). Batched A1/A2 gathers per chunk.
#define EPB 1024
#define ECH 8
#define DEPTH 4
__global__ void __launch_bounds__(128) k_edge1(
                        const float* __restrict__ eattr,
                        const int* __restrict__ eidx,
                        const float* __restrict__ fcW,
                        const float* __restrict__ fcB) {
    __shared__ __align__(16) float attr_s[DEPTH][ECH][44];  // 5632 B, col41 zeroed
    __shared__ int idx_s[DEPTH][2][ECH];                    // src,dst per buffer
    int tid = threadIdx.x;  // 128 -> output column c

    // packed weight k-pairs: w2[j] = (W[2j,c], W[2j+1,c]); pair 20 = (W[40,c], 0)
    unsigned long long w2[21];
#pragma unroll
    for (int j = 0; j < 20; j++) {
        float wa = fcW[(FCO + 2 * j) * FCO + tid];
        float wb = fcW[(FCO + 2 * j + 1) * FCO + tid];
        asm("mov.b64 %0, {%1,%2};" : "=l"(w2[j]) : "f"(wa), "f"(wb));
    }
    {
        float wa = fcW[(FCO + 40) * FCO + tid];
        asm("mov.b64 %0, {%1,%2};" : "=l"(w2[20]) : "f"(wa), "f"(0.0f));
    }
    float b = fcB[tid];
    float s0 = 0.f, s1 = 0.f, q0 = 0.f, q1 = 0.f;

    // zero padding column 41 in all DEPTH*ECH rows (read as hi lane of pair 20)
    if (tid < DEPTH * ECH) attr_s[tid >> 3][tid & 7][41] = 0.f;

    int e0 = blockIdx.x * EPB;

    // async-stage chunk [ce0, ce0+8) into ring buffer; ALWAYS commits a group
    auto stage = [&](int ce0) {
        if (ce0 < NE) {
            int buf = (ce0 >> 3) & (DEPTH - 1);
            const float* gbase = eattr + (size_t)ce0 * NBR;
            for (int t = tid; t < ECH * NBR; t += 128) {
                int i = t / NBR, k = t - i * NBR;
                uint32_t sa = (uint32_t)__cvta_generic_to_shared(&attr_s[buf][i][k]);
                asm volatile("cp.async.ca.shared.global [%0], [%1], 4;"
                             :: "r"(sa), "l"(gbase + t));
            }
            if (tid < ECH) {
                uint32_t sa = (uint32_t)__cvta_generic_to_shared(&idx_s[buf][0][tid]);
                asm volatile("cp.async.ca.shared.global [%0], [%1], 4;"
                             :: "r"(sa), "l"(eidx + ce0 + tid));
            } else if (tid < 2 * ECH) {
                uint32_t sa = (uint32_t)__cvta_generic_to_shared(&idx_s[buf][1][tid - ECH]);
                asm volatile("cp.async.ca.shared.global [%0], [%1], 4;"
                             :: "r"(sa), "l"(eidx + NE + ce0 + tid - ECH));
            }
        }
        asm volatile("cp.async.commit_group;" ::: "memory");
    };

    // prologue: stage chunks 0..2 (3 committed groups)
    stage(e0);
    stage(e0 + ECH);
    stage(e0 + 2 * ECH);

    const int nch = EPB / ECH;   // 128
    for (int ch = 0; ch < nch; ch++) {
        // prior iteration's trailing barrier guarantees compute(ch-1) done in
        // all warps before we overwrite its ring slot (= slot of ch+3)
        stage(e0 + (ch + 3) * ECH);
        asm volatile("cp.async.wait_group 3;" ::: "memory");  // chunk ch arrived
        __syncthreads();

        int cb = e0 + ch * ECH;
        if (cb < NE) {                      // chunks full-or-empty (NE%8==0)
            int buf = ch & (DEPTH - 1);
            // batched gathers: 16 LDGs in flight before any FMA work
            float base[ECH];
#pragma unroll
            for (int i = 0; i < ECH; i++)
                base[i] = b + g_A1[idx_s[buf][0][i] * FCO + tid]
                            + g_A2[idx_s[buf][1][i] * FCO + tid];
#pragma unroll
            for (int i = 0; i < ECH; i++) {
                unsigned long long acc;
                asm("mov.b64 %0, {%1,%2};" : "=l"(acc) : "f"(base[i]), "f"(0.0f));
                const ulonglong2* a16 = (const ulonglong2*)attr_s[buf][i];
#pragma unroll
                for (int j = 0; j < 10; j++) {
                    ulonglong2 u = a16[j];
                    asm("fma.rn.f32x2 %0, %1, %2, %0;" : "+l"(acc) : "l"(u.x), "l"(w2[2 * j]));
                    asm("fma.rn.f32x2 %0, %1, %2, %0;" : "+l"(acc) : "l"(u.y), "l"(w2[2 * j + 1]));
                }
                {
                    unsigned long long u20 = ((const unsigned long long*)attr_s[buf][i])[20];
                    asm("fma.rn.f32x2 %0, %1, %2, %0;" : "+l"(acc) : "l"(u20), "l"(w2[20]));
                }
                float lo, hi;
                asm("mov.b64 {%0,%1}, %2;" : "=f"(lo), "=f"(hi) : "l"(acc));
                float h = lo + hi;
                g_h[(size_t)(cb + i) * FCO + tid] = h;
                if (i & 1) { s1 += h; q1 = fmaf(h, h, q1); }
                else       { s0 += h; q0 = fmaf(h, h, q0); }
            }
        }
        __syncthreads();
    }
    atomicAdd(&g_s1[tid], (double)(s0 + s1));
    atomicAdd(&g_q1[tid], (double)(q0 + q1));
}

// ---------------- K3: finalize bn1 scale/shift --------------------------------
__global__ void k_bn1fin(const float* __restrict__ g1, const float* __restrict__ b1) {
    int c = threadIdx.x;
    double mean = g_s1[c] / (double)NE;
    double var  = g_q1[c] / (double)NE - mean * mean;
    float sc = g1[c] * (float)(1.0 / sqrt(var + (double)EPS));
    g_bn1_scale[c] = sc;
    g_bn1_shift[c] = b1[c] - (float)mean * sc;
}

__device__ __forceinline__ float sigm(float x)  { return __fdividef(1.f, 1.f + __expf(-x)); }
__device__ __forceinline__ float softp(float x) { return fmaxf(x, 0.f) + __logf(1.f + __expf(-fabsf(x))); }

// ---------------- K4: edge pass 2 — msg + scatter into summed ----------------
__global__ void k_edge2(const int* __restrict__ eidx) {
    int gtid = blockIdx.x * blockDim.x + threadIdx.x;
    int e = gtid >> 4;          // 16 threads per edge
    int q = gtid & 15;          // 4 columns per thread
    if (e >= NE) return;
    const float4* h4 = (const float4*)(g_h + (size_t)e * FCO);
    float4 hf = h4[q];
    float4 hc = h4[16 + q];
    int c0 = q * 4;
    float4 m;
    {
        float f0 = g_bn1_scale[c0 + 0] * hf.x + g_bn1_shift[c0 + 0];
        float f1 = g_bn1_scale[c0 + 1] * hf.y + g_bn1_shift[c0 + 1];
        float f2 = g_bn1_scale[c0 + 2] * hf.z + g_bn1_shift[c0 + 2];
        float f3 = g_bn1_scale[c0 + 3] * hf.w + g_bn1_shift[c0 + 3];
        float g0 = g_bn1_scale[64 + c0 + 0] * hc.x + g_bn1_shift[64 + c0 + 0];
        float g1 = g_bn1_scale[64 + c0 + 1] * hc.y + g_bn1_shift[64 + c0 + 1];
        float g2 = g_bn1_scale[64 + c0 + 2] * hc.z + g_bn1_shift[64 + c0 + 2];
        float g3 = g_bn1_scale[64 + c0 + 3] * hc.w + g_bn1_shift[64 + c0 + 3];
        m.x = sigm(f0) * softp(g0);
        m.y = sigm(f1) * softp(g1);
        m.z = sigm(f2) * softp(g2);
        m.w = sigm(f3) * softp(g3);
    }
    int src = eidx[e];
    float* dst = g_summed + src * ATOMD + c0;
    asm volatile("red.global.add.v4.f32 [%0], {%1,%2,%3,%4};"
                 :: "l"(dst), "f"(m.x), "f"(m.y), "f"(m.z), "f"(m.w) : "memory");
}

// ---------------- K5: bn2 stats over summed -----------------------------------
__global__ void k_bn2stats() {
    int c    = threadIdx.x & 63;
    int row0 = blockIdx.x * (blockDim.x >> 6) + (threadIdx.x >> 6);
    int strd = gridDim.x * (blockDim.x >> 6);
    float s = 0.f, q = 0.f;
    for (int r = row0; r < NN; r += strd) {
        float v = g_summed[r * ATOMD + c];
        s += v; q += v * v;
    }
    atomicAdd(&g_s2[c], (double)s);
    atomicAdd(&g_q2[c], (double)q);
}

__global__ void k_bn2fin(const float* __restrict__ g2, const float* __restrict__ b2) {
    int c = threadIdx.x;
    double mean = g_s2[c] / (double)NN;
    double var  = g_q2[c] / (double)NN - mean * mean;
    float sc = g2[c] * (float)(1.0 / sqrt(var + (double)EPS));
    g_bn2_scale[c] = sc;
    g_bn2_shift[c] = b2[c] - (float)mean * sc;
}

// ---------------- K6: atom_out + silu + logits ---------------------------------
__global__ void k_node2(float* __restrict__ out,
                        const float* __restrict__ attW,
                        const float* __restrict__ attB) {
    int tid  = threadIdx.x;          // 256 -> 4 nodes
    int node = blockIdx.x * 4 + (tid >> 6);
    int c    = tid & 63;
    __shared__ float sh[4][2];
    float part = 0.f;
    if (node < NN) {
        float v  = g_summed[node * ATOMD + c];
        float ao = g_bn2_scale[c] * v + g_bn2_shift[c];
        out[node * ATOMD + c] = ao;
        float h = ao * sigm(ao);
        g_hnode[node * ATOMD + c] = h;
        part = h * attW[c];
    }
#pragma unroll
    for (int off = 16; off; off >>= 1)
        part += __shfl_down_sync(0xffffffff, part, off);
    if ((tid & 31) == 0) sh[tid >> 6][(tid >> 5) & 1] = part;
    __syncthreads();
    if (tid < 4) {
        int n2 = blockIdx.x * 4 + tid;
        if (n2 < NN) g_logits[n2] = sh[tid][0] + sh[tid][1] + attB[0];
    }
}

// ---------------- K7: per-graph softmax attention pooling ----------------------
__global__ void k_graph(float* __restrict__ out,
                        const int* __restrict__ batch,
                        const float* __restrict__ outW,
                        const float* __restrict__ outB) {
    int g   = blockIdx.x;
    int tid = threadIdx.x;           // 128
    __shared__ int lo_s, hi_s;
    __shared__ float red[128];
    if (tid == 0) {
        int lo = 0, hi = NN;
        while (lo < hi) { int md = (lo + hi) >> 1; if (batch[md] < g) lo = md + 1; else hi = md; }
        lo_s = lo;
        int lo2 = lo, hi2 = NN;
        while (lo2 < hi2) { int md = (lo2 + hi2) >> 1; if (batch[md] < g + 1) lo2 = md + 1; else hi2 = md; }
        hi_s = lo2;
    }
    __syncthreads();
    int lo = lo_s, hi = hi_s;
    if (lo >= hi) { if (tid == 0) out[NN * ATOMD + g] = outB[0]; return; }

    float m = -INFINITY;
    for (int n = lo + tid; n < hi; n += 128) m = fmaxf(m, g_logits[n]);
    red[tid] = m; __syncthreads();
    for (int s = 64; s; s >>= 1) { if (tid < s) red[tid] = fmaxf(red[tid], red[tid + s]); __syncthreads(); }
    m = red[0]; __syncthreads();

    float ssum = 0.f;
    for (int n = lo + tid; n < hi; n += 128) ssum += expf(g_logits[n] - m);
    red[tid] = ssum; __syncthreads();
    for (int s = 64; s; s >>= 1) { if (tid < s) red[tid] += red[tid + s]; __syncthreads(); }
    float denom = red[0]; __syncthreads();

    int c = tid & 63, half = tid >> 6;
    float acc = 0.f;
    for (int n = lo + half; n < hi; n += 2) {
        float alpha = expf(g_logits[n] - m) / denom;
        acc += alpha * g_hnode[n * ATOMD + c];
    }
    red[tid] = acc * outW[c]; __syncthreads();
    for (int s = 64; s; s >>= 1) { if (tid < s) red[tid] += red[tid + s]; __syncthreads(); }
    if (tid == 0) out[NN * ATOMD + g] = red[0] + outB[0];
}

// ---------------- launch --------------------------------------------------------
extern "C" void kernel_launch(void* const* d_in, const int* in_sizes, int n_in,
                              void* d_out, int out_size) {
    const float *x, *eattr, *lowf, *embW, *embB, *fcW, *fcB;
    const float *bn1g, *bn1b, *bn2g, *bn2b, *attW, *attB, *outW, *outB;
    const int *eidx, *batch;

    if (in_sizes[3] == 2 * NE) {
        // setup_inputs dict order
        x     = (const float*)d_in[0];  eattr = (const float*)d_in[1];
        lowf  = (const float*)d_in[2];  eidx  = (const int*)  d_in[3];
        batch = (const int*)  d_in[4];  embW  = (const float*)d_in[5];
        embB  = (const float*)d_in[6];  fcW   = (const float*)d_in[7];
        fcB   = (const float*)d_in[8];  bn1g  = (const float*)d_in[9];
        bn1b  = (const float*)d_in[10]; bn2g  = (const float*)d_in[11];
        bn2b  = (const float*)d_in[12]; attW  = (const float*)d_in[13];
        attB  = (const float*)d_in[14]; outW  = (const float*)d_in[15];
        outB  = (const float*)d_in[16];
    } else {
        // reference-signature order
        x     = (const float*)d_in[0];  eattr = (const float*)d_in[1];
        lowf  = (const float*)d_in[2];  embW  = (const float*)d_in[3];
        embB  = (const float*)d_in[4];  fcW   = (const float*)d_in[5];
        fcB   = (const float*)d_in[6];  bn1g  = (const float*)d_in[7];
        bn1b  = (const float*)d_in[8];  bn2g  = (const float*)d_in[9];
        bn2b  = (const float*)d_in[10]; attW  = (const float*)d_in[11];
        attB  = (const float*)d_in[12]; outW  = (const float*)d_in[13];
        outB  = (const float*)d_in[14]; eidx  = (const int*)  d_in[15];
        batch = (const int*)  d_in[16];
    }

    float* out = (float*)d_out;

    k_init<<<2048, 512>>>();
    k_embed<<<(NN + NPB - 1) / NPB, 256>>>(x, lowf, embW, embB);
    {
        dim3 grid((NN + NPB - 1) / NPB, 2);
        k_proj<<<grid, 256>>>(fcW);
    }
    k_edge1<<<(NE + EPB - 1) / EPB, 128>>>(eattr, eidx, fcW, fcB);
    k_bn1fin<<<1, FCO>>>(bn1g, bn1b);
    k_edge2<<<(NE * 16 + 255) / 256, 256>>>(eidx);
    k_bn2stats<<<128, 256>>>();
    k_bn2fin<<<1, ATOMD>>>(bn2g, bn2b);
    k_node2<<<(NN + 3) / 4, 256>>>(out, attW, attB);
    k_graph<<<NG, 128>>>(out, batch, outW, outB);
}

// round 12
// speedup vs baseline: 1.7138x; 1.3086x over previous
#include <cuda_runtime.h>
#include <math.h>
#include <stdint.h>

#define NN    50000
#define NE    1000000
#define NG    256
#define ORIG  92
#define ATOMD 64
#define NBR   41
#define FCO   128
#define EPS   1e-5f

// ---------------- scratch (static device globals; no allocation) -------------
__device__ float  g_af[NN * ATOMD];          // atom_fea
__device__ float  g_A1[NN * FCO];            // atom_fea @ fc_W[0:64]
__device__ float  g_A2[NN * FCO];            // atom_fea @ fc_W[64:128]
__device__ float  g_h[(size_t)NE * FCO];     // pre-BN edge hidden (512 MB)
__device__ float  g_summed[NN * ATOMD];      // segment_sum(msg, src)
__device__ float  g_hnode[NN * ATOMD];       // silu(atom_out)
__device__ float  g_logits[NN];
__device__ double g_s1[FCO], g_q1[FCO];      // bn1 sum / sumsq
__device__ double g_s2[ATOMD], g_q2[ATOMD];  // bn2 sum / sumsq
__device__ float  g_bn1_scale[FCO], g_bn1_shift[FCO];
__device__ float  g_bn2_scale[ATOMD], g_bn2_shift[ATOMD];

// ---------------- K0: zero the per-launch accumulators -----------------------
__global__ void k_init() {
    int stride = gridDim.x * blockDim.x;
    for (int i = blockIdx.x * blockDim.x + threadIdx.x; i < NN * ATOMD; i += stride)
        g_summed[i] = 0.f;
    int t = blockIdx.x * blockDim.x + threadIdx.x;
    if (t < FCO)   { g_s1[t] = 0.0; g_q1[t] = 0.0; }
    if (t < ATOMD) { g_s2[t] = 0.0; g_q2[t] = 0.0; }
}

// ---------------- K1a: atom_fea = x @ emb_W + emb_b + lower_f ----------------
#define NPB 16
__global__ void k_embed(const float* __restrict__ x,
                        const float* __restrict__ lower_f,
                        const float* __restrict__ embW,
                        const float* __restrict__ embB) {
    __shared__ __align__(16) float embW_s[ORIG * ATOMD];   // 23552 B
    __shared__ __align__(16) float x_s[NPB * ORIG];        // 5888 B
    int tid = threadIdx.x;  // 256
    int n0  = blockIdx.x * NPB;
    for (int i = tid; i < ORIG * ATOMD; i += 256) embW_s[i] = embW[i];
    for (int i = tid; i < NPB * ORIG; i += 256) {
        int node = n0 + i / ORIG;
        x_s[i] = (node < NN) ? x[node * ORIG + (i % ORIG)] : 0.f;
    }
    __syncthreads();
    for (int t = tid; t < NPB * ATOMD; t += 256) {
        int i = t >> 6, c = t & 63, node = n0 + i;
        if (node >= NN) continue;
        float acc = 0.f;
        const float4* x4 = (const float4*)(x_s + i * ORIG);
#pragma unroll
        for (int k4 = 0; k4 < ORIG / 4; k4++) {
            float4 xv = x4[k4];
            int k = k4 * 4;
            acc += xv.x * embW_s[(k + 0) * ATOMD + c];
            acc += xv.y * embW_s[(k + 1) * ATOMD + c];
            acc += xv.z * embW_s[(k + 2) * ATOMD + c];
            acc += xv.w * embW_s[(k + 3) * ATOMD + c];
        }
        g_af[node * ATOMD + c] = acc + embB[c] + lower_f[node * ATOMD + c];
    }
}

// ---------------- K1b: A1/A2 = atom_fea @ Wa/Wb (register-tiled) -------------
__global__ void k_proj(const float* __restrict__ fcW) {
    __shared__ __align__(16) float W_s[ATOMD * FCO];   // 32 KB
    __shared__ __align__(16) float at_s[NPB * ATOMD];  // 4 KB
    int tid   = threadIdx.x;        // 256
    int which = blockIdx.y;         // 0 -> A1 (rows 0..63), 1 -> A2 (rows 64..127)
    int n0    = blockIdx.x * NPB;
    const float* Wsrc = fcW + which * ATOMD * FCO;
    for (int i = tid; i < ATOMD * FCO; i += 256) W_s[i] = Wsrc[i];
    for (int i = tid; i < NPB * ATOMD; i += 256) {
        int node = n0 + (i >> 6);
        at_s[i] = (node < NN) ? g_af[node * ATOMD + (i & 63)] : 0.f;
    }
    __syncthreads();
    int j = tid & 127, ig = tid >> 7;   // 2 node-groups of 8
    float acc[8];
#pragma unroll
    for (int r = 0; r < 8; r++) acc[r] = 0.f;
    for (int c = 0; c < ATOMD; c++) {
        float w = W_s[c * FCO + j];
#pragma unroll
        for (int r = 0; r < 8; r++)
            acc[r] += at_s[(ig + 2 * r) * ATOMD + c] * w;
    }
    float* dst = which ? g_A2 : g_A1;
#pragma unroll
    for (int r = 0; r < 8; r++) {
        int node = n0 + ig + 2 * r;
        if (node < NN) dst[node * FCO + j] = acc[r];
    }
}

// ---------------- K2: edge pass 1 — h = A1[src]+A2[dst]+attr@W3+b, stats -----
// cp.async ring staging (proven) + 2 independent f32x2 chains per edge
// (dependent chain 84 -> ~44 cyc) + 4-edge gather sub-batches (register diet).
#define EPB 1024
#define ECH 8
#define DEPTH 4
__global__ void __launch_bounds__(128) k_edge1(
                        const float* __restrict__ eattr,
                        const int* __restrict__ eidx,
                        const float* __restrict__ fcW,
                        const float* __restrict__ fcB) {
    __shared__ __align__(16) float attr_s[DEPTH][ECH][44];  // 5632 B, col41 zeroed
    __shared__ int idx_s[DEPTH][2][ECH];                    // src,dst per buffer
    int tid = threadIdx.x;  // 128 -> output column c

    // packed weight k-pairs: w2[j] = (W[2j,c], W[2j+1,c]); pair 20 = (W[40,c], 0)
    unsigned long long w2[21];
#pragma unroll
    for (int j = 0; j < 20; j++) {
        float wa = fcW[(FCO + 2 * j) * FCO + tid];
        float wb = fcW[(FCO + 2 * j + 1) * FCO + tid];
        asm("mov.b64 %0, {%1,%2};" : "=l"(w2[j]) : "f"(wa), "f"(wb));
    }
    {
        float wa = fcW[(FCO + 40) * FCO + tid];
        asm("mov.b64 %0, {%1,%2};" : "=l"(w2[20]) : "f"(wa), "f"(0.0f));
    }
    float b = fcB[tid];
    float s0 = 0.f, s1 = 0.f, q0 = 0.f, q1 = 0.f;

    // zero padding column 41 in all DEPTH*ECH rows (read as hi lane of pair 20)
    if (tid < DEPTH * ECH) attr_s[tid >> 3][tid & 7][41] = 0.f;

    int e0 = blockIdx.x * EPB;

    // async-stage chunk [ce0, ce0+8) into ring buffer; ALWAYS commits a group
    auto stage = [&](int ce0) {
        if (ce0 < NE) {
            int buf = (ce0 >> 3) & (DEPTH - 1);
            const float* gbase = eattr + (size_t)ce0 * NBR;
            for (int t = tid; t < ECH * NBR; t += 128) {
                int i = t / NBR, k = t - i * NBR;
                uint32_t sa = (uint32_t)__cvta_generic_to_shared(&attr_s[buf][i][k]);
                asm volatile("cp.async.ca.shared.global [%0], [%1], 4;"
                             :: "r"(sa), "l"(gbase + t));
            }
            if (tid < ECH) {
                uint32_t sa = (uint32_t)__cvta_generic_to_shared(&idx_s[buf][0][tid]);
                asm volatile("cp.async.ca.shared.global [%0], [%1], 4;"
                             :: "r"(sa), "l"(eidx + ce0 + tid));
            } else if (tid < 2 * ECH) {
                uint32_t sa = (uint32_t)__cvta_generic_to_shared(&idx_s[buf][1][tid - ECH]);
                asm volatile("cp.async.ca.shared.global [%0], [%1], 4;"
                             :: "r"(sa), "l"(eidx + NE + ce0 + tid - ECH));
            }
        }
        asm volatile("cp.async.commit_group;" ::: "memory");
    };

    // prologue: stage chunks 0..2 (3 committed groups)
    stage(e0);
    stage(e0 + ECH);
    stage(e0 + 2 * ECH);

    const int nch = EPB / ECH;   // 128
    for (int ch = 0; ch < nch; ch++) {
        // prior iteration's trailing barrier guarantees compute(ch-1) done in
        // all warps before we overwrite its ring slot (= slot of ch+3)
        stage(e0 + (ch + 3) * ECH);
        asm volatile("cp.async.wait_group 3;" ::: "memory");  // chunk ch arrived
        __syncthreads();

        int cb = e0 + ch * ECH;
        if (cb < NE) {                      // chunks full-or-empty (NE%8==0)
            int buf = ch & (DEPTH - 1);
            // process in 2 sub-batches of 4 edges: 8 LDGs in flight, fewer regs
#pragma unroll
            for (int g = 0; g < 2; g++) {
                float base[4];
#pragma unroll
                for (int u = 0; u < 4; u++) {
                    int i = g * 4 + u;
                    base[u] = b + g_A1[idx_s[buf][0][i] * FCO + tid]
                                + g_A2[idx_s[buf][1][i] * FCO + tid];
                }
#pragma unroll
                for (int u = 0; u < 4; u++) {
                    int i = g * 4 + u;
                    // two independent f32x2 chains per edge
                    unsigned long long acc0, acc1;
                    asm("mov.b64 %0, {%1,%2};" : "=l"(acc0) : "f"(base[u]), "f"(0.0f));
                    asm("mov.b64 %0, {%1,%1};" : "=l"(acc1) : "f"(0.0f));
                    const ulonglong2* a16 = (const ulonglong2*)attr_s[buf][i];
#pragma unroll
                    for (int j = 0; j < 10; j++) {
                        ulonglong2 uu = a16[j];
                        asm("fma.rn.f32x2 %0, %1, %2, %0;" : "+l"(acc0) : "l"(uu.x), "l"(w2[2 * j]));
                        asm("fma.rn.f32x2 %0, %1, %2, %0;" : "+l"(acc1) : "l"(uu.y), "l"(w2[2 * j + 1]));
                    }
                    {
                        unsigned long long u20 = ((const unsigned long long*)attr_s[buf][i])[20];
                        asm("fma.rn.f32x2 %0, %1, %2, %0;" : "+l"(acc0) : "l"(u20), "l"(w2[20]));
                    }
                    asm("add.rn.f32x2 %0, %0, %1;" : "+l"(acc0) : "l"(acc1));
                    float lo, hi;
                    asm("mov.b64 {%0,%1}, %2;" : "=f"(lo), "=f"(hi) : "l"(acc0));
                    float h = lo + hi;
                    g_h[(size_t)(cb + i) * FCO + tid] = h;
                    if (u & 1) { s1 += h; q1 = fmaf(h, h, q1); }
                    else       { s0 += h; q0 = fmaf(h, h, q0); }
                }
            }
        }
        __syncthreads();
    }
    atomicAdd(&g_s1[tid], (double)(s0 + s1));
    atomicAdd(&g_q1[tid], (double)(q0 + q1));
}

// ---------------- K3: finalize bn1 scale/shift --------------------------------
__global__ void k_bn1fin(const float* __restrict__ g1, const float* __restrict__ b1) {
    int c = threadIdx.x;
    double mean = g_s1[c] / (double)NE;
    double var  = g_q1[c] / (double)NE - mean * mean;
    float sc = g1[c] * (float)(1.0 / sqrt(var + (double)EPS));
    g_bn1_scale[c] = sc;
    g_bn1_shift[c] = b1[c] - (float)mean * sc;
}

__device__ __forceinline__ float sigm(float x)  { return __fdividef(1.f, 1.f + __expf(-x)); }
__device__ __forceinline__ float softp(float x) { return fmaxf(x, 0.f) + __logf(1.f + __expf(-fabsf(x))); }

// ---------------- K4: edge pass 2 — msg + scatter into summed ----------------
__global__ void k_edge2(const int* __restrict__ eidx) {
    int gtid = blockIdx.x * blockDim.x + threadIdx.x;
    int e = gtid >> 4;          // 16 threads per edge
    int q = gtid & 15;          // 4 columns per thread
    if (e >= NE) return;
    const float4* h4 = (const float4*)(g_h + (size_t)e * FCO);
    float4 hf = h4[q];
    float4 hc = h4[16 + q];
    int c0 = q * 4;
    float4 m;
    {
        float f0 = g_bn1_scale[c0 + 0] * hf.x + g_bn1_shift[c0 + 0];
        float f1 = g_bn1_scale[c0 + 1] * hf.y + g_bn1_shift[c0 + 1];
        float f2 = g_bn1_scale[c0 + 2] * hf.z + g_bn1_shift[c0 + 2];
        float f3 = g_bn1_scale[c0 + 3] * hf.w + g_bn1_shift[c0 + 3];
        float g0 = g_bn1_scale[64 + c0 + 0] * hc.x + g_bn1_shift[64 + c0 + 0];
        float g1 = g_bn1_scale[64 + c0 + 1] * hc.y + g_bn1_shift[64 + c0 + 1];
        float g2 = g_bn1_scale[64 + c0 + 2] * hc.z + g_bn1_shift[64 + c0 + 2];
        float g3 = g_bn1_scale[64 + c0 + 3] * hc.w + g_bn1_shift[64 + c0 + 3];
        m.x = sigm(f0) * softp(g0);
        m.y = sigm(f1) * softp(g1);
        m.z = sigm(f2) * softp(g2);
        m.w = sigm(f3) * softp(g3);
    }
    int src = eidx[e];
    float* dst = g_summed + src * ATOMD + c0;
    asm volatile("red.global.add.v4.f32 [%0], {%1,%2,%3,%4};"
                 :: "l"(dst), "f"(m.x), "f"(m.y), "f"(m.z), "f"(m.w) : "memory");
}

// ---------------- K5: bn2 stats over summed -----------------------------------
__global__ void k_bn2stats() {
    int c    = threadIdx.x & 63;
    int row0 = blockIdx.x * (blockDim.x >> 6) + (threadIdx.x >> 6);
    int strd = gridDim.x * (blockDim.x >> 6);
    float s = 0.f, q = 0.f;
    for (int r = row0; r < NN; r += strd) {
        float v = g_summed[r * ATOMD + c];
        s += v; q += v * v;
    }
    atomicAdd(&g_s2[c], (double)s);
    atomicAdd(&g_q2[c], (double)q);
}

__global__ void k_bn2fin(const float* __restrict__ g2, const float* __restrict__ b2) {
    int c = threadIdx.x;
    double mean = g_s2[c] / (double)NN;
    double var  = g_q2[c] / (double)NN - mean * mean;
    float sc = g2[c] * (float)(1.0 / sqrt(var + (double)EPS));
    g_bn2_scale[c] = sc;
    g_bn2_shift[c] = b2[c] - (float)mean * sc;
}

// ---------------- K6: atom_out + silu + logits ---------------------------------
__global__ void k_node2(float* __restrict__ out,
                        const float* __restrict__ attW,
                        const float* __restrict__ attB) {
    int tid  = threadIdx.x;          // 256 -> 4 nodes
    int node = blockIdx.x * 4 + (tid >> 6);
    int c    = tid & 63;
    __shared__ float sh[4][2];
    float part = 0.f;
    if (node < NN) {
        float v  = g_summed[node * ATOMD + c];
        float ao = g_bn2_scale[c] * v + g_bn2_shift[c];
        out[node * ATOMD + c] = ao;
        float h = ao * sigm(ao);
        g_hnode[node * ATOMD + c] = h;
        part = h * attW[c];
    }
#pragma unroll
    for (int off = 16; off; off >>= 1)
        part += __shfl_down_sync(0xffffffff, part, off);
    if ((tid & 31) == 0) sh[tid >> 6][(tid >> 5) & 1] = part;
    __syncthreads();
    if (tid < 4) {
        int n2 = blockIdx.x * 4 + tid;
        if (n2 < NN) g_logits[n2] = sh[tid][0] + sh[tid][1] + attB[0];
    }
}

// ---------------- K7: per-graph softmax attention pooling ----------------------
__global__ void k_graph(float* __restrict__ out,
                        const int* __restrict__ batch,
                        const float* __restrict__ outW,
                        const float* __restrict__ outB) {
    int g   = blockIdx.x;
    int tid = threadIdx.x;           // 128
    __shared__ int lo_s, hi_s;
    __shared__ float red[128];
    if (tid == 0) {
        int lo = 0, hi = NN;
        while (lo < hi) { int md = (lo + hi) >> 1; if (batch[md] < g) lo = md + 1; else hi = md; }
        lo_s = lo;
        int lo2 = lo, hi2 = NN;
        while (lo2 < hi2) { int md = (lo2 + hi2) >> 1; if (batch[md] < g + 1) lo2 = md + 1; else hi2 = md; }
        hi_s = lo2;
    }
    __syncthreads();
    int lo = lo_s, hi = hi_s;
    if (lo >= hi) { if (tid == 0) out[NN * ATOMD + g] = outB[0]; return; }

    float m = -INFINITY;
    for (int n = lo + tid; n < hi; n += 128) m = fmaxf(m, g_logits[n]);
    red[tid] = m; __syncthreads();
    for (int s = 64; s; s >>= 1) { if (tid < s) red[tid] = fmaxf(red[tid], red[tid + s]); __syncthreads(); }
    m = red[0]; __syncthreads();

    float ssum = 0.f;
    for (int n = lo + tid; n < hi; n += 128) ssum += expf(g_logits[n] - m);
    red[tid] = ssum; __syncthreads();
    for (int s = 64; s; s >>= 1) { if (tid < s) red[tid] += red[tid + s]; __syncthreads(); }
    float denom = red[0]; __syncthreads();

    int c = tid & 63, half = tid >> 6;
    float acc = 0.f;
    for (int n = lo + half; n < hi; n += 2) {
        float alpha = expf(g_logits[n] - m) / denom;
        acc += alpha * g_hnode[n * ATOMD + c];
    }
    red[tid] = acc * outW[c]; __syncthreads();
    for (int s = 64; s; s >>= 1) { if (tid < s) red[tid] += red[tid + s]; __syncthreads(); }
    if (tid == 0) out[NN * ATOMD + g] = red[0] + outB[0];
}

// ---------------- launch --------------------------------------------------------
extern "C" void kernel_launch(void* const* d_in, const int* in_sizes, int n_in,
                              void* d_out, int out_size) {
    const float *x, *eattr, *lowf, *embW, *embB, *fcW, *fcB;
    const float *bn1g, *bn1b, *bn2g, *bn2b, *attW, *attB, *outW, *outB;
    const int *eidx, *batch;

    if (in_sizes[3] == 2 * NE) {
        // setup_inputs dict order
        x     = (const float*)d_in[0];  eattr = (const float*)d_in[1];
        lowf  = (const float*)d_in[2];  eidx  = (const int*)  d_in[3];
        batch = (const int*)  d_in[4];  embW  = (const float*)d_in[5];
        embB  = (const float*)d_in[6];  fcW   = (const float*)d_in[7];
        fcB   = (const float*)d_in[8];  bn1g  = (const float*)d_in[9];
        bn1b  = (const float*)d_in[10]; bn2g  = (const float*)d_in[11];
        bn2b  = (const float*)d_in[12]; attW  = (const float*)d_in[13];
        attB  = (const float*)d_in[14]; outW  = (const float*)d_in[15];
        outB  = (const float*)d_in[16];
    } else {
        // reference-signature order
        x     = (const float*)d_in[0];  eattr = (const float*)d_in[1];
        lowf  = (const float*)d_in[2];  embW  = (const float*)d_in[3];
        embB  = (const float*)d_in[4];  fcW   = (const float*)d_in[5];
        fcB   = (const float*)d_in[6];  bn1g  = (const float*)d_in[7];
        bn1b  = (const float*)d_in[8];  bn2g  = (const float*)d_in[9];
        bn2b  = (const float*)d_in[10]; attW  = (const float*)d_in[11];
        attB  = (const float*)d_in[12]; outW  = (const float*)d_in[13];
        outB  = (const float*)d_in[14]; eidx  = (const int*)  d_in[15];
        batch = (const int*)  d_in[16];
    }

    float* out = (float*)d_out;

    k_init<<<2048, 512>>>();
    k_embed<<<(NN + NPB - 1) / NPB, 256>>>(x, lowf, embW, embB);
    {
        dim3 grid((NN + NPB - 1) / NPB, 2);
        k_proj<<<grid, 256>>>(fcW);
    }
    k_edge1<<<(NE + EPB - 1) / EPB, 128>>>(eattr, eidx, fcW, fcB);
    k_bn1fin<<<1, FCO>>>(bn1g, bn1b);
    k_edge2<<<(NE * 16 + 255) / 256, 256>>>(eidx);
    k_bn2stats<<<128, 256>>>();
    k_bn2fin<<<1, ATOMD>>>(bn2g, bn2b);
    k_node2<<<(NN + 3) / 4, 256>>>(out, attW, attB);
    k_graph<<<NG, 128>>>(out, batch, outW, outB);
}